// round 13
// baseline (speedup 1.0000x reference)
#include <cuda_runtime.h>
#include <cuda_bf16.h>

#define BQ 1024

// ---------- packed fp32x2 FMA (Blackwell FFMA2) ----------
union F2U { float2 f; unsigned long long u; };
__device__ __forceinline__ float2 ffma2(float2 a, float2 b, float2 c) {
    F2U A, B, C, D;
    A.f = a; B.f = b; C.f = c;
    asm("fma.rn.f32x2 %0, %1, %2, %3;" : "=l"(D.u) : "l"(A.u), "l"(B.u), "l"(C.u));
    return D.f;
}
__device__ __forceinline__ float2 mf2(float x, float y) { float2 r; r.x = x; r.y = y; return r; }

// ---------- cp.async helpers ----------
__device__ __forceinline__ unsigned su32(const void* p) {
    return (unsigned)__cvta_generic_to_shared(p);
}
#define CP16(dst_u32, src_ptr) \
    asm volatile("cp.async.cg.shared.global [%0], [%1], 16;\n" :: "r"(dst_u32), "l"(src_ptr))
#define CPCOMMIT() asm volatile("cp.async.commit_group;\n" ::: "memory")
#define CPWAIT0()  asm volatile("cp.async.wait_group 0;\n" ::: "memory")
#define PAIRBAR(id) asm volatile("bar.sync %0, 64;" :: "r"(id) : "memory")

// ---------- folded weights + scratch ----------
__device__ float g_s[64];
__device__ float g_AkT[512];    // [j][c]
__device__ float g_AqT[512];    // [j][c]
__device__ float g_ApT[64];     // [j][i]
__device__ float g_cb[8];
__device__ float g_Wv2[4096];   // [c][d] = Wv[d][c]

__device__ float g_vh[33554432];   // [524288][64]  k@WvT + s
__device__ float g_hk[4194304];    // [524288][8]   k@AkT
__device__ float g_hq[524288];     // [65536][8]    q@AqT

// 4 independent blocks: 0 -> s, 1 -> AkT+Wv2, 2 -> AqT, 3 -> ApT+cb
__global__ void precompute_kernel(
    const float* __restrict__ strength, const float* __restrict__ str_w,
    const float* __restrict__ str_b,
    const float* __restrict__ q_tbl, const float* __restrict__ k_tbl,
    const float* __restrict__ v_tbl,
    const float* __restrict__ attn_w1, const float* __restrict__ attn_b1,
    const float* __restrict__ pos_w2, const float* __restrict__ pos_b2,
    const int* __restrict__ embed_id)
{
    const int t = threadIdx.x;
    const int e = embed_id[0];
    const int bid = blockIdx.x;

    if (bid == 0) {
        __shared__ float red[256];
        const int o = t & 63, p = t >> 6;
        float acc = 0.f;
        for (int i = p * 128; i < (p + 1) * 128; ++i) acc += strength[i] * str_w[i * 64 + o];
        red[t] = acc;
        __syncthreads();
        if (t < 64) g_s[t] = red[t] + red[t + 64] + red[t + 128] + red[t + 192] + str_b[t];
    } else if (bid == 1) {
        for (int idx = t; idx < 512; idx += 256) {
            const int j = idx >> 6, c = idx & 63;
            float ak = 0.f;
            for (int dd = 0; dd < 64; ++dd)
                ak += k_tbl[e * 4096 + dd * 64 + c] * attn_w1[dd * 8 + j];
            g_AkT[idx] = ak;
        }
        for (int i = t; i < 4096; i += 256) {
            const int c = i >> 6, dd = i & 63;
            g_Wv2[c * 64 + dd] = v_tbl[e * 4096 + dd * 64 + c];
        }
    } else if (bid == 2) {
        for (int idx = t; idx < 512; idx += 256) {
            const int j = idx >> 6, c = idx & 63;
            float aq = 0.f;
            for (int dd = 0; dd < 64; ++dd)
                aq += q_tbl[e * 4096 + dd * 64 + c] * attn_w1[dd * 8 + j];
            g_AqT[idx] = aq;
        }
    } else {
        if (t < 64) {
            const int j = t >> 3, i = t & 7;
            float ap = 0.f;
            for (int dd = 0; dd < 64; ++dd) ap += pos_w2[i * 64 + dd] * attn_w1[dd * 8 + j];
            g_ApT[j * 8 + i] = ap;
        }
        if (t >= 64 && t < 72) {
            const int j = t - 64;
            float cb = attn_b1[j];
            for (int dd = 0; dd < 64; ++dd) cb += pos_b2[dd] * attn_w1[dd * 8 + j];
            g_cb[j] = cb;
        }
    }
}

// ---------- VH = k@WvT + s, HK = k@AkT ----------
// 256 k-rows per CTA, 4 x 64-row tiles, cp.async double buffer, occ 4.
#define VK0   0          // 64*68 = 4352
#define VK1   4352       // 4352
#define VW2   8704       // 4096  [c][d] stride 64 (no pad; intra-row reads)
#define VAK   12800      // 544   [j][c] stride 68
#define VS    13344      // 64
#define VFLO  13408
#define VBYTES (VFLO * 4)

__global__ __launch_bounds__(256, 4)
void vh_kernel(const float* __restrict__ k)
{
    extern __shared__ __align__(16) float sm[];
    float* s_w2 = sm + VW2;
    float* s_ak = sm + VAK;
    float* s_s  = sm + VS;

    const int tid = threadIdx.x;
    const long row00 = (long)blockIdx.x * 256;

    // prefetch tile 0
    {
        const float4* kg = (const float4*)(k + row00 * 64);
        #pragma unroll
        for (int r = 0; r < 4; ++r) {
            const int i = tid + 256 * r;
            CP16(su32(sm + VK0 + (i >> 4) * 68 + (i & 15) * 4), kg + i);
        }
        CPCOMMIT();
    }

    // stage weights once per CTA
    for (int i = tid; i < 4096; i += 256) s_w2[i] = g_Wv2[i];
    for (int i = tid; i < 512; i += 256)
        s_ak[(i >> 6) * 68 + (i & 63)] = g_AkT[i];
    if (tid < 64) s_s[tid] = g_s[tid];

    const int lane = tid & 31, w = tid >> 5;
    const int dg = lane & 7, rg = lane >> 3;
    const int dbase = (w >> 2) * 32 + dg * 4;
    const int rquart = (w & 3) * 16;
    const int j = tid & 7, rr = tid >> 3;

    for (int t = 0; t < 4; ++t) {
        const int bb = t & 1;
        float* s_k = sm + (bb ? VK1 : VK0);
        const long row0 = row00 + t * 64;

        CPWAIT0();
        __syncthreads();

        if (t < 3) {
            float* n_k = sm + (bb ? VK0 : VK1);
            const float4* kg = (const float4*)(k + (row0 + 64) * 64);
            #pragma unroll
            for (int r = 0; r < 4; ++r) {
                const int i = tid + 256 * r;
                CP16(su32(n_k + (i >> 4) * 68 + (i & 15) * 4), kg + i);
            }
            CPCOMMIT();
        }

        // ---- VH: 4 rows x 4 d per thread ----
        float2 acc[4][2];
        #pragma unroll
        for (int r = 0; r < 4; ++r) { acc[r][0] = mf2(0.f, 0.f); acc[r][1] = mf2(0.f, 0.f); }

        #pragma unroll
        for (int c4 = 0; c4 < 16; ++c4) {
            float4 k4[4];
            #pragma unroll
            for (int r = 0; r < 4; ++r)
                k4[r] = *(const float4*)&s_k[(rquart + rg + 4 * r) * 68 + c4 * 4];
            #pragma unroll
            for (int cs = 0; cs < 4; ++cs) {
                const float4 w4 = *(const float4*)&s_w2[(c4 * 4 + cs) * 64 + dbase];
                const float2 wlo = mf2(w4.x, w4.y), whi = mf2(w4.z, w4.w);
                #pragma unroll
                for (int r = 0; r < 4; ++r) {
                    const float kv = (cs == 0) ? k4[r].x : (cs == 1) ? k4[r].y
                                   : (cs == 2) ? k4[r].z : k4[r].w;
                    acc[r][0] = ffma2(mf2(kv, kv), wlo, acc[r][0]);
                    acc[r][1] = ffma2(mf2(kv, kv), whi, acc[r][1]);
                }
            }
        }
        const float4 s4 = *(const float4*)&s_s[dbase];
        #pragma unroll
        for (int r = 0; r < 4; ++r) {
            float4 o;
            o.x = acc[r][0].x + s4.x; o.y = acc[r][0].y + s4.y;
            o.z = acc[r][1].x + s4.z; o.w = acc[r][1].y + s4.w;
            *(float4*)&g_vh[(row0 + rquart + rg + 4 * r) * 64 + dbase] = o;
        }

        // ---- HK: 2 rows per thread ----
        #pragma unroll
        for (int half = 0; half < 2; ++half) {
            const int row = rr + 32 * half;
            float2 a0 = mf2(0.f, 0.f), a1 = mf2(0.f, 0.f);
            const float4* kr = (const float4*)&s_k[row * 68];
            const float4* ar = (const float4*)&s_ak[j * 68];
            #pragma unroll
            for (int c4 = 0; c4 < 16; ++c4) {
                const float4 kk = kr[c4], aa = ar[c4];
                a0 = ffma2(mf2(kk.x, kk.y), mf2(aa.x, aa.y), a0);
                a1 = ffma2(mf2(kk.z, kk.w), mf2(aa.z, aa.w), a1);
            }
            g_hk[(row0 + row) * 8 + j] = (a0.x + a1.x) + (a0.y + a1.y);
        }
    }
}

// HQ = q @ AqT ; 64 q-rows per block.
__global__ __launch_bounds__(256, 2)
void hq_kernel(const float* __restrict__ q)
{
    __shared__ __align__(16) float s_q[64 * 68];
    __shared__ __align__(16) float s_aq[8 * 68];

    const int tid = threadIdx.x;
    const long row0 = (long)blockIdx.x * 64;

    const float4* qg = (const float4*)(q + row0 * 64);
    for (int i = tid; i < 1024; i += 256)
        CP16(su32(&s_q[(i >> 4) * 68 + (i & 15) * 4]), qg + i);
    CPCOMMIT();
    for (int i = tid; i < 512; i += 256)
        s_aq[(i >> 6) * 68 + (i & 63)] = g_AqT[i];
    CPWAIT0();
    __syncthreads();

    const int j = tid & 7, rr = tid >> 3;
    #pragma unroll
    for (int half = 0; half < 2; ++half) {
        const int row = rr + 32 * half;
        float2 a0 = mf2(0.f, 0.f), a1 = mf2(0.f, 0.f);
        const float4* qr = (const float4*)&s_q[row * 68];
        const float4* ar = (const float4*)&s_aq[j * 68];
        #pragma unroll
        for (int c4 = 0; c4 < 16; ++c4) {
            const float4 qq = qr[c4], aa = ar[c4];
            a0 = ffma2(mf2(qq.x, qq.y), mf2(aa.x, aa.y), a0);
            a1 = ffma2(mf2(qq.z, qq.w), mf2(aa.z, aa.w), a1);
        }
        g_hq[(row0 + row) * 8 + j] = (a0.x + a1.x) + (a0.y + a1.y);
    }
}

// Fused softmax kernel; per-chunk phases use 64-thread named barriers
// (all A1->A2->B dependencies stay within the 64-thread ln-group),
// plus one CTA-wide barrier per chunk for buffer swap.
__global__ __launch_bounds__(256, 3)
void attn_main(
    const float* __restrict__ pos,
    const float* __restrict__ pos_w1, const float* __restrict__ pos_b1,
    const float* __restrict__ pos_w2, const float* __restrict__ pos_b2,
    const float* __restrict__ attn_w2, const float* __restrict__ attn_b2,
    const float* __restrict__ out_w, const float* __restrict__ out_b,
    const int* __restrict__ mask,
    float* __restrict__ out)
{
    __shared__ __align__(16) float s_vh[2][2048];   // [rv][64]
    __shared__ __align__(16) float s_pos[2][128];
    __shared__ __align__(16) float s_hk[2][256];    // [rv][8]
    __shared__ __align__(16) float s_hq[2][32];     // [ln][8]
    __shared__ __align__(16) float s_ph[256];       // [rv][8]
    __shared__ __align__(16) float s_hh[256];       // [rv][8]
    __shared__ float s_xall[32 * 65];               // [lrow][d], stride 65
    __shared__ __align__(16) float s_apT[64];
    __shared__ float s_pw1[32];
    __shared__ __align__(16) int s_mask[2][32];

    const int tid = threadIdx.x;
    const int b = blockIdx.x;
    const int nbase = blockIdx.y * 32;

    // ---- prefetch chunk 0 ----
    {
        const long base_n = (long)b * 64 + nbase;
        const float4* vhg = (const float4*)(g_vh + base_n * 512);
        CP16(su32(&s_vh[0][tid * 4]), vhg + tid);
        CP16(su32(&s_vh[0][(tid + 256) * 4]), vhg + tid + 256);
        if (tid < 64)  CP16(su32(&s_hk[0][tid * 4]), (const float4*)(g_hk + base_n * 64) + tid);
        else if (tid < 96)  { const int i = tid - 64; CP16(su32(&s_pos[0][i * 4]), (const float4*)(pos + base_n * 32) + i); }
        else if (tid < 104) { const int i = tid - 96; CP16(su32(&s_hq[0][i * 4]), (const float4*)(g_hq + base_n * 8) + i); }
        else if (tid < 112) { const int i = tid - 104; CP16(su32(&s_mask[0][i * 4]), (const int4*)(mask + base_n * 8) + i); }
        CPCOMMIT();
    }

    // ---- one-time staging ----
    if (tid < 64) s_apT[tid] = g_ApT[tid];
    if (tid < 32) s_pw1[tid] = pos_w1[tid];

    const int d  = tid & 63;
    const int j  = tid & 7;
    const int vA = (tid >> 3) & 7;
    const int ln = tid >> 6;
    const int ln8v = ln * 8 + vA;
    const int barid = 1 + ln;

    float2 aw2r[4], pw2r[4];
    #pragma unroll
    for (int p = 0; p < 4; ++p) {
        aw2r[p] = mf2(attn_w2[(2 * p) * 64 + d], attn_w2[(2 * p + 1) * 64 + d]);
        pw2r[p] = mf2(pos_w2[(2 * p) * 64 + d], pos_w2[(2 * p + 1) * 64 + d]);
    }
    const float ab2d = attn_b2[d];
    const float pb2d = pos_b2[d];
    const float cbj  = g_cb[j];
    const float pb1j = pos_b1[j];

    for (int chunk = 0; chunk < 8; ++chunk) {
        const int bb = chunk & 1;
        const long base_n = (long)b * 64 + nbase + chunk * 4;

        CPWAIT0();
        __syncthreads();   // CTA-wide: buffers ready, prior readers done

        // ---- prefetch next chunk ----
        if (chunk < 7) {
            const long bn1 = base_n + 4;
            const int nb = 1 - bb;
            const float4* vhg = (const float4*)(g_vh + bn1 * 512);
            CP16(su32(&s_vh[nb][tid * 4]), vhg + tid);
            CP16(su32(&s_vh[nb][(tid + 256) * 4]), vhg + tid + 256);
            if (tid < 64)  CP16(su32(&s_hk[nb][tid * 4]), (const float4*)(g_hk + bn1 * 64) + tid);
            else if (tid < 96)  { const int i = tid - 64; CP16(su32(&s_pos[nb][i * 4]), (const float4*)(pos + bn1 * 32) + i); }
            else if (tid < 104) { const int i = tid - 96; CP16(su32(&s_hq[nb][i * 4]), (const float4*)(g_hq + bn1 * 8) + i); }
            else if (tid < 112) { const int i = tid - 104; CP16(su32(&s_mask[nb][i * 4]), (const int4*)(mask + bn1 * 8) + i); }
            CPCOMMIT();
        }

        // ---- phase A1: pos-MLP hidden ----
        {
            const float4 p4 = *reinterpret_cast<const float4*>(&s_pos[bb][ln8v * 4]);
            float acc = pb1j;
            acc += p4.x * s_pw1[0 * 8 + j];
            acc += p4.y * s_pw1[1 * 8 + j];
            acc += p4.z * s_pw1[2 * 8 + j];
            acc += p4.w * s_pw1[3 * 8 + j];
            s_ph[ln8v * 8 + j] = fmaxf(acc, 0.f);
        }
        PAIRBAR(barid);

        // ---- phase A2: attn hidden = relu(hk - hq + ph@Ap + cb) ----
        {
            float2 acc0 = mf2(s_hk[bb][ln8v * 8 + j] - s_hq[bb][ln * 8 + j] + cbj, 0.f);
            float2 acc1 = mf2(0.f, 0.f);
            const float4* phr = reinterpret_cast<const float4*>(s_ph + ln8v * 8);
            const float4  h0 = phr[0], h1 = phr[1];
            const float4* apr = reinterpret_cast<const float4*>(s_apT + j * 8);
            const float4  a0 = apr[0], a1 = apr[1];
            acc0 = ffma2(mf2(h0.x, h0.y), mf2(a0.x, a0.y), acc0);
            acc1 = ffma2(mf2(h0.z, h0.w), mf2(a0.z, a0.w), acc1);
            acc0 = ffma2(mf2(h1.x, h1.y), mf2(a1.x, a1.y), acc0);
            acc1 = ffma2(mf2(h1.z, h1.w), mf2(a1.z, a1.w), acc1);
            s_hh[ln8v * 8 + j] = fmaxf((acc0.x + acc1.x) + (acc0.y + acc1.y), 0.f);
        }
        PAIRBAR(barid);

        // ---- phase B: logits + val, softmax over V; write to s_xall ----
        {
            // per-thread mask bits for this ln-group (broadcast LDS)
            const int4 m0i = *reinterpret_cast<const int4*>(&s_mask[bb][ln * 8]);
            const int4 m1i = *reinterpret_cast<const int4*>(&s_mask[bb][ln * 8 + 4]);
            int mbits = 0;
            mbits |= (m0i.x != 0) << 0; mbits |= (m0i.y != 0) << 1;
            mbits |= (m0i.z != 0) << 2; mbits |= (m0i.w != 0) << 3;
            mbits |= (m1i.x != 0) << 4; mbits |= (m1i.y != 0) << 5;
            mbits |= (m1i.z != 0) << 6; mbits |= (m1i.w != 0) << 7;

            float logit[8], val[8];
            #pragma unroll
            for (int v = 0; v < 8; ++v) {
                const int rv = ln * 8 + v;
                const float4* hhr = reinterpret_cast<const float4*>(s_hh + rv * 8);
                const float4 h0 = hhr[0], h1 = hhr[1];
                float2 a2 = ffma2(mf2(h0.x, h0.y), aw2r[0], mf2(ab2d, 0.f));
                float2 a3 = ffma2(mf2(h0.z, h0.w), aw2r[1], mf2(0.f, 0.f));
                a2 = ffma2(mf2(h1.x, h1.y), aw2r[2], a2);
                a3 = ffma2(mf2(h1.z, h1.w), aw2r[3], a3);

                const float4* phr = reinterpret_cast<const float4*>(s_ph + rv * 8);
                const float4 p0 = phr[0], p1 = phr[1];
                float2 pv = ffma2(mf2(p0.x, p0.y), pw2r[0], mf2(pb2d, 0.f));
                float2 pw = ffma2(mf2(p0.z, p0.w), pw2r[1], mf2(0.f, 0.f));
                pv = ffma2(mf2(p1.x, p1.y), pw2r[2], pv);
                pw = ffma2(mf2(p1.z, p1.w), pw2r[3], pw);

                logit[v] = ((mbits >> v) & 1) ? ((a2.x + a3.x) + (a2.y + a3.y)) : -1e9f;
                val[v] = s_vh[bb][rv * 64 + d] + (pv.x + pw.x) + (pv.y + pw.y);
            }
            const float m01 = fmaxf(fmaxf(logit[0], logit[1]), fmaxf(logit[2], logit[3]));
            const float m23 = fmaxf(fmaxf(logit[4], logit[5]), fmaxf(logit[6], logit[7]));
            const float m = fmaxf(m01, m23);
            float ev[8];
            #pragma unroll
            for (int v = 0; v < 8; ++v) ev[v] = __expf(logit[v] - m);
            const float ssum = ((ev[0] + ev[1]) + (ev[2] + ev[3]))
                             + ((ev[4] + ev[5]) + (ev[6] + ev[7]));
            const float wacc = ((ev[0] * val[0] + ev[1] * val[1]) + (ev[2] * val[2] + ev[3] * val[3]))
                             + ((ev[4] * val[4] + ev[5] * val[5]) + (ev[6] * val[6] + ev[7] * val[7]));
            s_xall[(chunk * 4 + ln) * 65 + d] = __fdividef(wacc, ssum);
        }
        // next iteration's CPWAIT0 + __syncthreads closes this chunk
    }
    __syncthreads();

    // ---- deferred output GEMM: 32 rows x 64 d; out_w via __ldg ----
    {
        const int dblk = (tid & 15) * 4;
        const int rp = tid >> 4;                 // 0..15
        const float4 ob4 = *reinterpret_cast<const float4*>(out_b + dblk);
        float2 a0 = mf2(ob4.x, ob4.y), a1 = mf2(ob4.z, ob4.w);
        float2 b0 = a0, b1 = a1;
        const float* x0p = s_xall + rp * 65;
        const float* x1p = s_xall + (rp + 16) * 65;
        #pragma unroll
        for (int c = 0; c < 64; ++c) {
            const float4 w4 = __ldg(reinterpret_cast<const float4*>(out_w + c * 64 + dblk));
            const float2 wlo = mf2(w4.x, w4.y), whi = mf2(w4.z, w4.w);
            const float xv0 = x0p[c], xv1 = x1p[c];
            a0 = ffma2(mf2(xv0, xv0), wlo, a0);
            a1 = ffma2(mf2(xv0, xv0), whi, a1);
            b0 = ffma2(mf2(xv1, xv1), wlo, b0);
            b1 = ffma2(mf2(xv1, xv1), whi, b1);
        }
        const long nb0 = (long)b * 64 + nbase;
        float4 o;
        o.x = a0.x; o.y = a0.y; o.z = a1.x; o.w = a1.y;
        *reinterpret_cast<float4*>(out + (nb0 + rp) * 64 + dblk) = o;
        o.x = b0.x; o.y = b0.y; o.z = b1.x; o.w = b1.y;
        *reinterpret_cast<float4*>(out + (nb0 + rp + 16) * 64 + dblk) = o;
    }
}

extern "C" void kernel_launch(void* const* d_in, const int* in_sizes, int n_in,
                              void* d_out, int out_size)
{
    const float* q        = (const float*)d_in[0];
    const float* k        = (const float*)d_in[1];
    const float* pos      = (const float*)d_in[2];
    const float* strength = (const float*)d_in[3];
    const float* q_tbl    = (const float*)d_in[4];
    const float* k_tbl    = (const float*)d_in[5];
    const float* v_tbl    = (const float*)d_in[6];
    const float* pos_w1   = (const float*)d_in[7];
    const float* pos_b1   = (const float*)d_in[8];
    const float* pos_w2   = (const float*)d_in[9];
    const float* pos_b2   = (const float*)d_in[10];
    const float* attn_w1  = (const float*)d_in[11];
    const float* attn_b1  = (const float*)d_in[12];
    const float* attn_w2  = (const float*)d_in[13];
    const float* attn_b2  = (const float*)d_in[14];
    const float* out_w    = (const float*)d_in[15];
    const float* out_b    = (const float*)d_in[16];
    const float* str_w    = (const float*)d_in[17];
    const float* str_b    = (const float*)d_in[18];
    const int*   mask     = (const int*)d_in[19];
    const int*   embed_id = (const int*)d_in[20];
    float* out = (float*)d_out;

    static bool attr_set = false;
    if (!attr_set) {
        cudaFuncSetAttribute(vh_kernel, cudaFuncAttributeMaxDynamicSharedMemorySize, VBYTES);
        attr_set = true;
    }

    precompute_kernel<<<4, 256>>>(strength, str_w, str_b, q_tbl, k_tbl, v_tbl,
                                  attn_w1, attn_b1, pos_w2, pos_b2, embed_id);

    vh_kernel<<<2048, 256, VBYTES>>>(k);
    hq_kernel<<<1024, 256>>>(q);

    dim3 grid(BQ, 2);
    attn_main<<<grid, 256>>>(pos,
                             pos_w1, pos_b1, pos_w2, pos_b2,
                             attn_w2, attn_b2, out_w, out_b,
                             mask, out);
}

// round 15
// speedup vs baseline: 1.1960x; 1.1960x over previous
#include <cuda_runtime.h>
#include <cuda_bf16.h>

#define BQ 1024

// ---------- packed fp32x2 FMA (Blackwell FFMA2) ----------
union F2U { float2 f; unsigned long long u; };
__device__ __forceinline__ float2 ffma2(float2 a, float2 b, float2 c) {
    F2U A, B, C, D;
    A.f = a; B.f = b; C.f = c;
    asm("fma.rn.f32x2 %0, %1, %2, %3;" : "=l"(D.u) : "l"(A.u), "l"(B.u), "l"(C.u));
    return D.f;
}
__device__ __forceinline__ float2 mf2(float x, float y) { float2 r; r.x = x; r.y = y; return r; }

// ---------- cp.async helpers ----------
__device__ __forceinline__ unsigned su32(const void* p) {
    return (unsigned)__cvta_generic_to_shared(p);
}
#define CP16(dst_u32, src_ptr) \
    asm volatile("cp.async.cg.shared.global [%0], [%1], 16;\n" :: "r"(dst_u32), "l"(src_ptr))
#define CPCOMMIT() asm volatile("cp.async.commit_group;\n" ::: "memory")
#define CPWAIT0()  asm volatile("cp.async.wait_group 0;\n" ::: "memory")
#define PAIRBAR(id) asm volatile("bar.sync %0, 64;" :: "r"(id) : "memory")

// ---------- folded weights + scratch ----------
__device__ float g_s[64];
__device__ float g_AkT[512];    // [j][c]
__device__ float g_AqT[512];    // [j][c]
__device__ float g_ApT[64];     // [j][i]
__device__ float g_cb[8];
__device__ float g_Wv2[4096];   // [c][d] = Wv[d][c]

__device__ float g_vh[33554432];   // [524288][64]  k@WvT + s
__device__ float g_hk[4194304];    // [524288][8]   k@AkT
__device__ float g_hq[524288];     // [65536][8]    q@AqT

// 4 independent blocks: 0 -> s, 1 -> AkT+Wv2, 2 -> AqT, 3 -> ApT+cb
__global__ void precompute_kernel(
    const float* __restrict__ strength, const float* __restrict__ str_w,
    const float* __restrict__ str_b,
    const float* __restrict__ q_tbl, const float* __restrict__ k_tbl,
    const float* __restrict__ v_tbl,
    const float* __restrict__ attn_w1, const float* __restrict__ attn_b1,
    const float* __restrict__ pos_w2, const float* __restrict__ pos_b2,
    const int* __restrict__ embed_id)
{
    const int t = threadIdx.x;
    const int e = embed_id[0];
    const int bid = blockIdx.x;

    if (bid == 0) {
        __shared__ float red[256];
        const int o = t & 63, p = t >> 6;
        float acc = 0.f;
        for (int i = p * 128; i < (p + 1) * 128; ++i) acc += strength[i] * str_w[i * 64 + o];
        red[t] = acc;
        __syncthreads();
        if (t < 64) g_s[t] = red[t] + red[t + 64] + red[t + 128] + red[t + 192] + str_b[t];
    } else if (bid == 1) {
        for (int idx = t; idx < 512; idx += 256) {
            const int j = idx >> 6, c = idx & 63;
            float ak = 0.f;
            for (int dd = 0; dd < 64; ++dd)
                ak += k_tbl[e * 4096 + dd * 64 + c] * attn_w1[dd * 8 + j];
            g_AkT[idx] = ak;
        }
        for (int i = t; i < 4096; i += 256) {
            const int c = i >> 6, dd = i & 63;
            g_Wv2[c * 64 + dd] = v_tbl[e * 4096 + dd * 64 + c];
        }
    } else if (bid == 2) {
        for (int idx = t; idx < 512; idx += 256) {
            const int j = idx >> 6, c = idx & 63;
            float aq = 0.f;
            for (int dd = 0; dd < 64; ++dd)
                aq += q_tbl[e * 4096 + dd * 64 + c] * attn_w1[dd * 8 + j];
            g_AqT[idx] = aq;
        }
    } else {
        if (t < 64) {
            const int j = t >> 3, i = t & 7;
            float ap = 0.f;
            for (int dd = 0; dd < 64; ++dd) ap += pos_w2[i * 64 + dd] * attn_w1[dd * 8 + j];
            g_ApT[j * 8 + i] = ap;
        }
        if (t >= 64 && t < 72) {
            const int j = t - 64;
            float cb = attn_b1[j];
            for (int dd = 0; dd < 64; ++dd) cb += pos_b2[dd] * attn_w1[dd * 8 + j];
            g_cb[j] = cb;
        }
    }
}

// ---------- VH = k@WvT + s, HK = k@AkT ----------
// 256 k-rows per CTA, 4 x 64-row tiles, cp.async double buffer, occ 3 (R11 config).
#define VK0   0          // 64*68 = 4352
#define VK1   4352       // 4352
#define VW2   8704       // 4352  [c][d] stride 68
#define VAK   13056      // 544   [j][c] stride 68
#define VS    13600      // 64
#define VFLO  13664
#define VBYTES (VFLO * 4)

__global__ __launch_bounds__(256, 3)
void vh_kernel(const float* __restrict__ k)
{
    extern __shared__ __align__(16) float sm[];
    float* s_w2 = sm + VW2;
    float* s_ak = sm + VAK;
    float* s_s  = sm + VS;

    const int tid = threadIdx.x;
    const long row00 = (long)blockIdx.x * 256;

    // prefetch tile 0
    {
        const float4* kg = (const float4*)(k + row00 * 64);
        #pragma unroll
        for (int r = 0; r < 4; ++r) {
            const int i = tid + 256 * r;
            CP16(su32(sm + VK0 + (i >> 4) * 68 + (i & 15) * 4), kg + i);
        }
        CPCOMMIT();
    }

    // stage weights once per CTA
    for (int i = tid; i < 4096; i += 256)
        s_w2[(i >> 6) * 68 + (i & 63)] = g_Wv2[i];
    for (int i = tid; i < 512; i += 256)
        s_ak[(i >> 6) * 68 + (i & 63)] = g_AkT[i];
    if (tid < 64) s_s[tid] = g_s[tid];

    const int lane = tid & 31, w = tid >> 5;
    const int dg = lane & 7, rg = lane >> 3;
    const int dbase = (w >> 2) * 32 + dg * 4;
    const int rquart = (w & 3) * 16;
    const int j = tid & 7, rr = tid >> 3;

    for (int t = 0; t < 4; ++t) {
        const int bb = t & 1;
        float* s_k = sm + (bb ? VK1 : VK0);
        const long row0 = row00 + t * 64;

        CPWAIT0();
        __syncthreads();

        if (t < 3) {
            float* n_k = sm + (bb ? VK0 : VK1);
            const float4* kg = (const float4*)(k + (row0 + 64) * 64);
            #pragma unroll
            for (int r = 0; r < 4; ++r) {
                const int i = tid + 256 * r;
                CP16(su32(n_k + (i >> 4) * 68 + (i & 15) * 4), kg + i);
            }
            CPCOMMIT();
        }

        // ---- VH: 4 rows x 4 d per thread ----
        float2 acc[4][2];
        #pragma unroll
        for (int r = 0; r < 4; ++r) { acc[r][0] = mf2(0.f, 0.f); acc[r][1] = mf2(0.f, 0.f); }

        #pragma unroll
        for (int c4 = 0; c4 < 16; ++c4) {
            float4 k4[4];
            #pragma unroll
            for (int r = 0; r < 4; ++r)
                k4[r] = *(const float4*)&s_k[(rquart + rg + 4 * r) * 68 + c4 * 4];
            #pragma unroll
            for (int cs = 0; cs < 4; ++cs) {
                const float4 w4 = *(const float4*)&s_w2[(c4 * 4 + cs) * 68 + dbase];
                const float2 wlo = mf2(w4.x, w4.y), whi = mf2(w4.z, w4.w);
                #pragma unroll
                for (int r = 0; r < 4; ++r) {
                    const float kv = (cs == 0) ? k4[r].x : (cs == 1) ? k4[r].y
                                   : (cs == 2) ? k4[r].z : k4[r].w;
                    acc[r][0] = ffma2(mf2(kv, kv), wlo, acc[r][0]);
                    acc[r][1] = ffma2(mf2(kv, kv), whi, acc[r][1]);
                }
            }
        }
        const float4 s4 = *(const float4*)&s_s[dbase];
        #pragma unroll
        for (int r = 0; r < 4; ++r) {
            float4 o;
            o.x = acc[r][0].x + s4.x; o.y = acc[r][0].y + s4.y;
            o.z = acc[r][1].x + s4.z; o.w = acc[r][1].y + s4.w;
            *(float4*)&g_vh[(row0 + rquart + rg + 4 * r) * 64 + dbase] = o;
        }

        // ---- HK: 2 rows per thread ----
        #pragma unroll
        for (int half = 0; half < 2; ++half) {
            const int row = rr + 32 * half;
            float2 a0 = mf2(0.f, 0.f), a1 = mf2(0.f, 0.f);
            const float4* kr = (const float4*)&s_k[row * 68];
            const float4* ar = (const float4*)&s_ak[j * 68];
            #pragma unroll
            for (int c4 = 0; c4 < 16; ++c4) {
                const float4 kk = kr[c4], aa = ar[c4];
                a0 = ffma2(mf2(kk.x, kk.y), mf2(aa.x, aa.y), a0);
                a1 = ffma2(mf2(kk.z, kk.w), mf2(aa.z, aa.w), a1);
            }
            g_hk[(row0 + row) * 8 + j] = (a0.x + a1.x) + (a0.y + a1.y);
        }
    }
}

// HQ = q @ AqT ; 64 q-rows per block.
__global__ __launch_bounds__(256, 2)
void hq_kernel(const float* __restrict__ q)
{
    __shared__ __align__(16) float s_q[64 * 68];
    __shared__ __align__(16) float s_aq[8 * 68];

    const int tid = threadIdx.x;
    const long row0 = (long)blockIdx.x * 64;

    const float4* qg = (const float4*)(q + row0 * 64);
    for (int i = tid; i < 1024; i += 256)
        CP16(su32(&s_q[(i >> 4) * 68 + (i & 15) * 4]), qg + i);
    CPCOMMIT();
    for (int i = tid; i < 512; i += 256)
        s_aq[(i >> 6) * 68 + (i & 63)] = g_AqT[i];
    CPWAIT0();
    __syncthreads();

    const int j = tid & 7, rr = tid >> 3;
    #pragma unroll
    for (int half = 0; half < 2; ++half) {
        const int row = rr + 32 * half;
        float2 a0 = mf2(0.f, 0.f), a1 = mf2(0.f, 0.f);
        const float4* qr = (const float4*)&s_q[row * 68];
        const float4* ar = (const float4*)&s_aq[j * 68];
        #pragma unroll
        for (int c4 = 0; c4 < 16; ++c4) {
            const float4 qq = qr[c4], aa = ar[c4];
            a0 = ffma2(mf2(qq.x, qq.y), mf2(aa.x, aa.y), a0);
            a1 = ffma2(mf2(qq.z, qq.w), mf2(aa.z, aa.w), a1);
        }
        g_hq[(row0 + row) * 8 + j] = (a0.x + a1.x) + (a0.y + a1.y);
    }
}

// Fused softmax kernel (R13 version, measured 94.8us): pair barriers,
// deferred output GEMM with __ldg(out_w).
__global__ __launch_bounds__(256, 3)
void attn_main(
    const float* __restrict__ pos,
    const float* __restrict__ pos_w1, const float* __restrict__ pos_b1,
    const float* __restrict__ pos_w2, const float* __restrict__ pos_b2,
    const float* __restrict__ attn_w2, const float* __restrict__ attn_b2,
    const float* __restrict__ out_w, const float* __restrict__ out_b,
    const int* __restrict__ mask,
    float* __restrict__ out)
{
    __shared__ __align__(16) float s_vh[2][2048];   // [rv][64]
    __shared__ __align__(16) float s_pos[2][128];
    __shared__ __align__(16) float s_hk[2][256];    // [rv][8]
    __shared__ __align__(16) float s_hq[2][32];     // [ln][8]
    __shared__ __align__(16) float s_ph[256];       // [rv][8]
    __shared__ __align__(16) float s_hh[256];       // [rv][8]
    __shared__ float s_xall[32 * 65];               // [lrow][d], stride 65
    __shared__ __align__(16) float s_apT[64];
    __shared__ float s_pw1[32];
    __shared__ __align__(16) int s_mask[2][32];

    const int tid = threadIdx.x;
    const int b = blockIdx.x;
    const int nbase = blockIdx.y * 32;

    // ---- prefetch chunk 0 ----
    {
        const long base_n = (long)b * 64 + nbase;
        const float4* vhg = (const float4*)(g_vh + base_n * 512);
        CP16(su32(&s_vh[0][tid * 4]), vhg + tid);
        CP16(su32(&s_vh[0][(tid + 256) * 4]), vhg + tid + 256);
        if (tid < 64)  CP16(su32(&s_hk[0][tid * 4]), (const float4*)(g_hk + base_n * 64) + tid);
        else if (tid < 96)  { const int i = tid - 64; CP16(su32(&s_pos[0][i * 4]), (const float4*)(pos + base_n * 32) + i); }
        else if (tid < 104) { const int i = tid - 96; CP16(su32(&s_hq[0][i * 4]), (const float4*)(g_hq + base_n * 8) + i); }
        else if (tid < 112) { const int i = tid - 104; CP16(su32(&s_mask[0][i * 4]), (const int4*)(mask + base_n * 8) + i); }
        CPCOMMIT();
    }

    // ---- one-time staging ----
    if (tid < 64) s_apT[tid] = g_ApT[tid];
    if (tid < 32) s_pw1[tid] = pos_w1[tid];

    const int d  = tid & 63;
    const int j  = tid & 7;
    const int vA = (tid >> 3) & 7;
    const int ln = tid >> 6;
    const int ln8v = ln * 8 + vA;
    const int barid = 1 + ln;

    float2 aw2r[4], pw2r[4];
    #pragma unroll
    for (int p = 0; p < 4; ++p) {
        aw2r[p] = mf2(attn_w2[(2 * p) * 64 + d], attn_w2[(2 * p + 1) * 64 + d]);
        pw2r[p] = mf2(pos_w2[(2 * p) * 64 + d], pos_w2[(2 * p + 1) * 64 + d]);
    }
    const float ab2d = attn_b2[d];
    const float pb2d = pos_b2[d];
    const float cbj  = g_cb[j];
    const float pb1j = pos_b1[j];

    for (int chunk = 0; chunk < 8; ++chunk) {
        const int bb = chunk & 1;
        const long base_n = (long)b * 64 + nbase + chunk * 4;

        CPWAIT0();
        __syncthreads();   // CTA-wide: buffers ready, prior readers done

        // ---- prefetch next chunk ----
        if (chunk < 7) {
            const long bn1 = base_n + 4;
            const int nb = 1 - bb;
            const float4* vhg = (const float4*)(g_vh + bn1 * 512);
            CP16(su32(&s_vh[nb][tid * 4]), vhg + tid);
            CP16(su32(&s_vh[nb][(tid + 256) * 4]), vhg + tid + 256);
            if (tid < 64)  CP16(su32(&s_hk[nb][tid * 4]), (const float4*)(g_hk + bn1 * 64) + tid);
            else if (tid < 96)  { const int i = tid - 64; CP16(su32(&s_pos[nb][i * 4]), (const float4*)(pos + bn1 * 32) + i); }
            else if (tid < 104) { const int i = tid - 96; CP16(su32(&s_hq[nb][i * 4]), (const float4*)(g_hq + bn1 * 8) + i); }
            else if (tid < 112) { const int i = tid - 104; CP16(su32(&s_mask[nb][i * 4]), (const int4*)(mask + bn1 * 8) + i); }
            CPCOMMIT();
        }

        // ---- phase A1: pos-MLP hidden ----
        {
            const float4 p4 = *reinterpret_cast<const float4*>(&s_pos[bb][ln8v * 4]);
            float acc = pb1j;
            acc += p4.x * s_pw1[0 * 8 + j];
            acc += p4.y * s_pw1[1 * 8 + j];
            acc += p4.z * s_pw1[2 * 8 + j];
            acc += p4.w * s_pw1[3 * 8 + j];
            s_ph[ln8v * 8 + j] = fmaxf(acc, 0.f);
        }
        PAIRBAR(barid);

        // ---- phase A2: attn hidden = relu(hk - hq + ph@Ap + cb) ----
        {
            float2 acc0 = mf2(s_hk[bb][ln8v * 8 + j] - s_hq[bb][ln * 8 + j] + cbj, 0.f);
            float2 acc1 = mf2(0.f, 0.f);
            const float4* phr = reinterpret_cast<const float4*>(s_ph + ln8v * 8);
            const float4  h0 = phr[0], h1 = phr[1];
            const float4* apr = reinterpret_cast<const float4*>(s_apT + j * 8);
            const float4  a0 = apr[0], a1 = apr[1];
            acc0 = ffma2(mf2(h0.x, h0.y), mf2(a0.x, a0.y), acc0);
            acc1 = ffma2(mf2(h0.z, h0.w), mf2(a0.z, a0.w), acc1);
            acc0 = ffma2(mf2(h1.x, h1.y), mf2(a1.x, a1.y), acc0);
            acc1 = ffma2(mf2(h1.z, h1.w), mf2(a1.z, a1.w), acc1);
            s_hh[ln8v * 8 + j] = fmaxf((acc0.x + acc1.x) + (acc0.y + acc1.y), 0.f);
        }
        PAIRBAR(barid);

        // ---- phase B: logits + val, softmax over V; write to s_xall ----
        {
            const int4 m0i = *reinterpret_cast<const int4*>(&s_mask[bb][ln * 8]);
            const int4 m1i = *reinterpret_cast<const int4*>(&s_mask[bb][ln * 8 + 4]);
            int mbits = 0;
            mbits |= (m0i.x != 0) << 0; mbits |= (m0i.y != 0) << 1;
            mbits |= (m0i.z != 0) << 2; mbits |= (m0i.w != 0) << 3;
            mbits |= (m1i.x != 0) << 4; mbits |= (m1i.y != 0) << 5;
            mbits |= (m1i.z != 0) << 6; mbits |= (m1i.w != 0) << 7;

            float logit[8], val[8];
            #pragma unroll
            for (int v = 0; v < 8; ++v) {
                const int rv = ln * 8 + v;
                const float4* hhr = reinterpret_cast<const float4*>(s_hh + rv * 8);
                const float4 h0 = hhr[0], h1 = hhr[1];
                float2 a2 = ffma2(mf2(h0.x, h0.y), aw2r[0], mf2(ab2d, 0.f));
                float2 a3 = ffma2(mf2(h0.z, h0.w), aw2r[1], mf2(0.f, 0.f));
                a2 = ffma2(mf2(h1.x, h1.y), aw2r[2], a2);
                a3 = ffma2(mf2(h1.z, h1.w), aw2r[3], a3);

                const float4* phr = reinterpret_cast<const float4*>(s_ph + rv * 8);
                const float4 p0 = phr[0], p1 = phr[1];
                float2 pv = ffma2(mf2(p0.x, p0.y), pw2r[0], mf2(pb2d, 0.f));
                float2 pw = ffma2(mf2(p0.z, p0.w), pw2r[1], mf2(0.f, 0.f));
                pv = ffma2(mf2(p1.x, p1.y), pw2r[2], pv);
                pw = ffma2(mf2(p1.z, p1.w), pw2r[3], pw);

                logit[v] = ((mbits >> v) & 1) ? ((a2.x + a3.x) + (a2.y + a3.y)) : -1e9f;
                val[v] = s_vh[bb][rv * 64 + d] + (pv.x + pw.x) + (pv.y + pw.y);
            }
            const float m01 = fmaxf(fmaxf(logit[0], logit[1]), fmaxf(logit[2], logit[3]));
            const float m23 = fmaxf(fmaxf(logit[4], logit[5]), fmaxf(logit[6], logit[7]));
            const float m = fmaxf(m01, m23);
            float ev[8];
            #pragma unroll
            for (int v = 0; v < 8; ++v) ev[v] = __expf(logit[v] - m);
            const float ssum = ((ev[0] + ev[1]) + (ev[2] + ev[3]))
                             + ((ev[4] + ev[5]) + (ev[6] + ev[7]));
            const float wacc = ((ev[0] * val[0] + ev[1] * val[1]) + (ev[2] * val[2] + ev[3] * val[3]))
                             + ((ev[4] * val[4] + ev[5] * val[5]) + (ev[6] * val[6] + ev[7] * val[7]));
            s_xall[(chunk * 4 + ln) * 65 + d] = __fdividef(wacc, ssum);
        }
        // next iteration's CPWAIT0 + __syncthreads closes this chunk
    }
    __syncthreads();

    // ---- deferred output GEMM: 32 rows x 64 d; out_w via __ldg ----
    {
        const int dblk = (tid & 15) * 4;
        const int rp = tid >> 4;                 // 0..15
        const float4 ob4 = *reinterpret_cast<const float4*>(out_b + dblk);
        float2 a0 = mf2(ob4.x, ob4.y), a1 = mf2(ob4.z, ob4.w);
        float2 b0 = a0, b1 = a1;
        const float* x0p = s_xall + rp * 65;
        const float* x1p = s_xall + (rp + 16) * 65;
        #pragma unroll
        for (int c = 0; c < 64; ++c) {
            const float4 w4 = __ldg(reinterpret_cast<const float4*>(out_w + c * 64 + dblk));
            const float2 wlo = mf2(w4.x, w4.y), whi = mf2(w4.z, w4.w);
            const float xv0 = x0p[c], xv1 = x1p[c];
            a0 = ffma2(mf2(xv0, xv0), wlo, a0);
            a1 = ffma2(mf2(xv0, xv0), whi, a1);
            b0 = ffma2(mf2(xv1, xv1), wlo, b0);
            b1 = ffma2(mf2(xv1, xv1), whi, b1);
        }
        const long nb0 = (long)b * 64 + nbase;
        float4 o;
        o.x = a0.x; o.y = a0.y; o.z = a1.x; o.w = a1.y;
        *reinterpret_cast<float4*>(out + (nb0 + rp) * 64 + dblk) = o;
        o.x = b0.x; o.y = b0.y; o.z = b1.x; o.w = b1.y;
        *reinterpret_cast<float4*>(out + (nb0 + rp + 16) * 64 + dblk) = o;
    }
}

extern "C" void kernel_launch(void* const* d_in, const int* in_sizes, int n_in,
                              void* d_out, int out_size)
{
    const float* q        = (const float*)d_in[0];
    const float* k        = (const float*)d_in[1];
    const float* pos      = (const float*)d_in[2];
    const float* strength = (const float*)d_in[3];
    const float* q_tbl    = (const float*)d_in[4];
    const float* k_tbl    = (const float*)d_in[5];
    const float* v_tbl    = (const float*)d_in[6];
    const float* pos_w1   = (const float*)d_in[7];
    const float* pos_b1   = (const float*)d_in[8];
    const float* pos_w2   = (const float*)d_in[9];
    const float* pos_b2   = (const float*)d_in[10];
    const float* attn_w1  = (const float*)d_in[11];
    const float* attn_b1  = (const float*)d_in[12];
    const float* attn_w2  = (const float*)d_in[13];
    const float* attn_b2  = (const float*)d_in[14];
    const float* out_w    = (const float*)d_in[15];
    const float* out_b    = (const float*)d_in[16];
    const float* str_w    = (const float*)d_in[17];
    const float* str_b    = (const float*)d_in[18];
    const int*   mask     = (const int*)d_in[19];
    const int*   embed_id = (const int*)d_in[20];
    float* out = (float*)d_out;

    static bool attr_set = false;
    if (!attr_set) {
        cudaFuncSetAttribute(vh_kernel, cudaFuncAttributeMaxDynamicSharedMemorySize, VBYTES);
        attr_set = true;
    }

    precompute_kernel<<<4, 256>>>(strength, str_w, str_b, q_tbl, k_tbl, v_tbl,
                                  attn_w1, attn_b1, pos_w2, pos_b2, embed_id);

    vh_kernel<<<2048, 256, VBYTES>>>(k);
    hq_kernel<<<1024, 256>>>(q);

    dim3 grid(BQ, 2);
    attn_main<<<grid, 256>>>(pos,
                             pos_w1, pos_b1, pos_w2, pos_b2,
                             attn_w2, attn_b2, out_w, out_b,
                             mask, out);
}

// round 16
// speedup vs baseline: 1.2998x; 1.0868x over previous
#include <cuda_runtime.h>
#include <cuda_bf16.h>

#define BQ 1024

// ---------- packed fp32x2 FMA (Blackwell FFMA2) ----------
union F2U { float2 f; unsigned long long u; };
__device__ __forceinline__ float2 ffma2(float2 a, float2 b, float2 c) {
    F2U A, B, C, D;
    A.f = a; B.f = b; C.f = c;
    asm("fma.rn.f32x2 %0, %1, %2, %3;" : "=l"(D.u) : "l"(A.u), "l"(B.u), "l"(C.u));
    return D.f;
}
__device__ __forceinline__ float2 mf2(float x, float y) { float2 r; r.x = x; r.y = y; return r; }

// ---------- cp.async helpers ----------
__device__ __forceinline__ unsigned su32(const void* p) {
    return (unsigned)__cvta_generic_to_shared(p);
}
#define CP16(dst_u32, src_ptr) \
    asm volatile("cp.async.cg.shared.global [%0], [%1], 16;\n" :: "r"(dst_u32), "l"(src_ptr))
#define CPCOMMIT() asm volatile("cp.async.commit_group;\n" ::: "memory")
#define CPWAIT0()  asm volatile("cp.async.wait_group 0;\n" ::: "memory")
#define PAIRBAR(id) asm volatile("bar.sync %0, 64;" :: "r"(id) : "memory")

// ---------- folded weights + scratch ----------
__device__ float g_s[64];
__device__ float g_AkT[512];    // [j][c]
__device__ float g_AqT[512];    // [j][c]
__device__ float g_ApT[64];     // [j][i]
__device__ float g_cb[8];
__device__ float g_Wv2[4096];   // [c][d] = Wv[d][c]

__device__ float g_vh[33554432];   // [524288][64]  k@WvT + s
__device__ float g_hk[4194304];    // [524288][8]   k@AkT
__device__ float g_hq[524288];     // [65536][8]    q@AqT

// 4 independent blocks: 0 -> s, 1 -> AkT+Wv2, 2 -> AqT, 3 -> ApT+cb
__global__ void precompute_kernel(
    const float* __restrict__ strength, const float* __restrict__ str_w,
    const float* __restrict__ str_b,
    const float* __restrict__ q_tbl, const float* __restrict__ k_tbl,
    const float* __restrict__ v_tbl,
    const float* __restrict__ attn_w1, const float* __restrict__ attn_b1,
    const float* __restrict__ pos_w2, const float* __restrict__ pos_b2,
    const int* __restrict__ embed_id)
{
    const int t = threadIdx.x;
    const int e = embed_id[0];
    const int bid = blockIdx.x;

    if (bid == 0) {
        __shared__ float red[256];
        const int o = t & 63, p = t >> 6;
        float acc = 0.f;
        for (int i = p * 128; i < (p + 1) * 128; ++i) acc += strength[i] * str_w[i * 64 + o];
        red[t] = acc;
        __syncthreads();
        if (t < 64) g_s[t] = red[t] + red[t + 64] + red[t + 128] + red[t + 192] + str_b[t];
    } else if (bid == 1) {
        for (int idx = t; idx < 512; idx += 256) {
            const int j = idx >> 6, c = idx & 63;
            float ak = 0.f;
            for (int dd = 0; dd < 64; ++dd)
                ak += k_tbl[e * 4096 + dd * 64 + c] * attn_w1[dd * 8 + j];
            g_AkT[idx] = ak;
        }
        for (int i = t; i < 4096; i += 256) {
            const int c = i >> 6, dd = i & 63;
            g_Wv2[c * 64 + dd] = v_tbl[e * 4096 + dd * 64 + c];
        }
    } else if (bid == 2) {
        for (int idx = t; idx < 512; idx += 256) {
            const int j = idx >> 6, c = idx & 63;
            float aq = 0.f;
            for (int dd = 0; dd < 64; ++dd)
                aq += q_tbl[e * 4096 + dd * 64 + c] * attn_w1[dd * 8 + j];
            g_AqT[idx] = aq;
        }
    } else {
        if (t < 64) {
            const int j = t >> 3, i = t & 7;
            float ap = 0.f;
            for (int dd = 0; dd < 64; ++dd) ap += pos_w2[i * 64 + dd] * attn_w1[dd * 8 + j];
            g_ApT[j * 8 + i] = ap;
        }
        if (t >= 64 && t < 72) {
            const int j = t - 64;
            float cb = attn_b1[j];
            for (int dd = 0; dd < 64; ++dd) cb += pos_b2[dd] * attn_w1[dd * 8 + j];
            g_cb[j] = cb;
        }
    }
}

// ---------- VH = k@WvT + s, HK fused into VH loop; blocks >= 2048 do HQ ----------
#define VK0   0          // 64*68 = 4352
#define VK1   4352       // 4352
#define VW2   8704       // 4352  [c][d] stride 68
#define VAK   13056      // 544   [j][c] stride 68
#define VS    13600      // 64
#define VFLO  13664
#define VBYTES (VFLO * 4)

__global__ __launch_bounds__(256, 3)
void vh_kernel(const float* __restrict__ k, const float* __restrict__ q)
{
    extern __shared__ __align__(16) float sm[];
    const int tid = threadIdx.x;

    if (blockIdx.x >= 2048) {
        // ---- HQ path: 64 q-rows per block ----
        float* s_q  = sm;            // stride 68
        float* s_aq = sm + 4352;     // [j][c] stride 68
        const long row0 = (long)(blockIdx.x - 2048) * 64;

        const float4* qg = (const float4*)(q + row0 * 64);
        for (int i = tid; i < 1024; i += 256)
            CP16(su32(&s_q[(i >> 4) * 68 + (i & 15) * 4]), qg + i);
        CPCOMMIT();
        for (int i = tid; i < 512; i += 256)
            s_aq[(i >> 6) * 68 + (i & 63)] = g_AqT[i];
        CPWAIT0();
        __syncthreads();

        const int j = tid & 7, rr = tid >> 3;
        #pragma unroll
        for (int half = 0; half < 2; ++half) {
            const int row = rr + 32 * half;
            float2 a0 = mf2(0.f, 0.f), a1 = mf2(0.f, 0.f);
            const float4* qr = (const float4*)&s_q[row * 68];
            const float4* ar = (const float4*)&s_aq[j * 68];
            #pragma unroll
            for (int c4 = 0; c4 < 16; ++c4) {
                const float4 qq = qr[c4], aa = ar[c4];
                a0 = ffma2(mf2(qq.x, qq.y), mf2(aa.x, aa.y), a0);
                a1 = ffma2(mf2(qq.z, qq.w), mf2(aa.z, aa.w), a1);
            }
            g_hq[(row0 + row) * 8 + j] = (a0.x + a1.x) + (a0.y + a1.y);
        }
        return;
    }

    // ---- VH path: 256 k-rows per CTA, 4 x 64-row tiles, double buffered ----
    float* s_w2 = sm + VW2;
    float* s_ak = sm + VAK;
    float* s_s  = sm + VS;

    const long row00 = (long)blockIdx.x * 256;

    // prefetch tile 0
    {
        const float4* kg = (const float4*)(k + row00 * 64);
        #pragma unroll
        for (int r = 0; r < 4; ++r) {
            const int i = tid + 256 * r;
            CP16(su32(sm + VK0 + (i >> 4) * 68 + (i & 15) * 4), kg + i);
        }
        CPCOMMIT();
    }

    // stage weights once per CTA
    for (int i = tid; i < 4096; i += 256)
        s_w2[(i >> 6) * 68 + (i & 63)] = g_Wv2[i];
    for (int i = tid; i < 512; i += 256)
        s_ak[(i >> 6) * 68 + (i & 63)] = g_AkT[i];
    if (tid < 64) s_s[tid] = g_s[tid];

    const int lane = tid & 31, w = tid >> 5;
    const int dg = lane & 7, rg = lane >> 3;
    const int dbase = (w >> 2) * 32 + dg * 4;
    const int rquart = (w & 3) * 16;
    const bool do_hk = (w < 4);          // warps 0-3 own hk for their quarter

    for (int t = 0; t < 4; ++t) {
        const int bb = t & 1;
        float* s_k = sm + (bb ? VK1 : VK0);
        const long row0 = row00 + t * 64;

        CPWAIT0();
        __syncthreads();

        if (t < 3) {
            float* n_k = sm + (bb ? VK0 : VK1);
            const float4* kg = (const float4*)(k + (row0 + 64) * 64);
            #pragma unroll
            for (int r = 0; r < 4; ++r) {
                const int i = tid + 256 * r;
                CP16(su32(n_k + (i >> 4) * 68 + (i & 15) * 4), kg + i);
            }
            CPCOMMIT();
        }

        // ---- VH (4 rows x 4 d per thread) with fused HK accumulation ----
        float2 acc[4][2];
        float hk[4];
        #pragma unroll
        for (int r = 0; r < 4; ++r) {
            acc[r][0] = mf2(0.f, 0.f); acc[r][1] = mf2(0.f, 0.f);
            hk[r] = 0.f;
        }

        #pragma unroll
        for (int c4 = 0; c4 < 16; ++c4) {
            float4 k4[4];
            #pragma unroll
            for (int r = 0; r < 4; ++r)
                k4[r] = *(const float4*)&s_k[(rquart + rg + 4 * r) * 68 + c4 * 4];

            if (do_hk) {
                const float4 a4 = *(const float4*)&s_ak[dg * 68 + c4 * 4];
                #pragma unroll
                for (int r = 0; r < 4; ++r)
                    hk[r] += k4[r].x * a4.x + k4[r].y * a4.y
                           + k4[r].z * a4.z + k4[r].w * a4.w;
            }

            #pragma unroll
            for (int cs = 0; cs < 4; ++cs) {
                const float4 w4 = *(const float4*)&s_w2[(c4 * 4 + cs) * 68 + dbase];
                const float2 wlo = mf2(w4.x, w4.y), whi = mf2(w4.z, w4.w);
                #pragma unroll
                for (int r = 0; r < 4; ++r) {
                    const float kv = (cs == 0) ? k4[r].x : (cs == 1) ? k4[r].y
                                   : (cs == 2) ? k4[r].z : k4[r].w;
                    acc[r][0] = ffma2(mf2(kv, kv), wlo, acc[r][0]);
                    acc[r][1] = ffma2(mf2(kv, kv), whi, acc[r][1]);
                }
            }
        }
        const float4 s4 = *(const float4*)&s_s[dbase];
        #pragma unroll
        for (int r = 0; r < 4; ++r) {
            float4 o;
            o.x = acc[r][0].x + s4.x; o.y = acc[r][0].y + s4.y;
            o.z = acc[r][1].x + s4.z; o.w = acc[r][1].y + s4.w;
            *(float4*)&g_vh[(row0 + rquart + rg + 4 * r) * 64 + dbase] = o;
        }
        if (do_hk) {
            #pragma unroll
            for (int r = 0; r < 4; ++r)
                g_hk[(row0 + rquart + rg + 4 * r) * 8 + dg] = hk[r];
        }
    }
}

// Fused softmax kernel (R13 version, measured 94.5us): pair barriers,
// deferred output GEMM with __ldg(out_w).
__global__ __launch_bounds__(256, 3)
void attn_main(
    const float* __restrict__ pos,
    const float* __restrict__ pos_w1, const float* __restrict__ pos_b1,
    const float* __restrict__ pos_w2, const float* __restrict__ pos_b2,
    const float* __restrict__ attn_w2, const float* __restrict__ attn_b2,
    const float* __restrict__ out_w, const float* __restrict__ out_b,
    const int* __restrict__ mask,
    float* __restrict__ out)
{
    __shared__ __align__(16) float s_vh[2][2048];   // [rv][64]
    __shared__ __align__(16) float s_pos[2][128];
    __shared__ __align__(16) float s_hk[2][256];    // [rv][8]
    __shared__ __align__(16) float s_hq[2][32];     // [ln][8]
    __shared__ __align__(16) float s_ph[256];       // [rv][8]
    __shared__ __align__(16) float s_hh[256];       // [rv][8]
    __shared__ float s_xall[32 * 65];               // [lrow][d], stride 65
    __shared__ __align__(16) float s_apT[64];
    __shared__ float s_pw1[32];
    __shared__ __align__(16) int s_mask[2][32];

    const int tid = threadIdx.x;
    const int b = blockIdx.x;
    const int nbase = blockIdx.y * 32;

    // ---- prefetch chunk 0 ----
    {
        const long base_n = (long)b * 64 + nbase;
        const float4* vhg = (const float4*)(g_vh + base_n * 512);
        CP16(su32(&s_vh[0][tid * 4]), vhg + tid);
        CP16(su32(&s_vh[0][(tid + 256) * 4]), vhg + tid + 256);
        if (tid < 64)  CP16(su32(&s_hk[0][tid * 4]), (const float4*)(g_hk + base_n * 64) + tid);
        else if (tid < 96)  { const int i = tid - 64; CP16(su32(&s_pos[0][i * 4]), (const float4*)(pos + base_n * 32) + i); }
        else if (tid < 104) { const int i = tid - 96; CP16(su32(&s_hq[0][i * 4]), (const float4*)(g_hq + base_n * 8) + i); }
        else if (tid < 112) { const int i = tid - 104; CP16(su32(&s_mask[0][i * 4]), (const int4*)(mask + base_n * 8) + i); }
        CPCOMMIT();
    }

    // ---- one-time staging ----
    if (tid < 64) s_apT[tid] = g_ApT[tid];
    if (tid < 32) s_pw1[tid] = pos_w1[tid];

    const int d  = tid & 63;
    const int j  = tid & 7;
    const int vA = (tid >> 3) & 7;
    const int ln = tid >> 6;
    const int ln8v = ln * 8 + vA;
    const int barid = 1 + ln;

    float2 aw2r[4], pw2r[4];
    #pragma unroll
    for (int p = 0; p < 4; ++p) {
        aw2r[p] = mf2(attn_w2[(2 * p) * 64 + d], attn_w2[(2 * p + 1) * 64 + d]);
        pw2r[p] = mf2(pos_w2[(2 * p) * 64 + d], pos_w2[(2 * p + 1) * 64 + d]);
    }
    const float ab2d = attn_b2[d];
    const float pb2d = pos_b2[d];
    const float cbj  = g_cb[j];
    const float pb1j = pos_b1[j];

    for (int chunk = 0; chunk < 8; ++chunk) {
        const int bb = chunk & 1;
        const long base_n = (long)b * 64 + nbase + chunk * 4;

        CPWAIT0();
        __syncthreads();   // CTA-wide: buffers ready, prior readers done

        // ---- prefetch next chunk ----
        if (chunk < 7) {
            const long bn1 = base_n + 4;
            const int nb = 1 - bb;
            const float4* vhg = (const float4*)(g_vh + bn1 * 512);
            CP16(su32(&s_vh[nb][tid * 4]), vhg + tid);
            CP16(su32(&s_vh[nb][(tid + 256) * 4]), vhg + tid + 256);
            if (tid < 64)  CP16(su32(&s_hk[nb][tid * 4]), (const float4*)(g_hk + bn1 * 64) + tid);
            else if (tid < 96)  { const int i = tid - 64; CP16(su32(&s_pos[nb][i * 4]), (const float4*)(pos + bn1 * 32) + i); }
            else if (tid < 104) { const int i = tid - 96; CP16(su32(&s_hq[nb][i * 4]), (const float4*)(g_hq + bn1 * 8) + i); }
            else if (tid < 112) { const int i = tid - 104; CP16(su32(&s_mask[nb][i * 4]), (const int4*)(mask + bn1 * 8) + i); }
            CPCOMMIT();
        }

        // ---- phase A1: pos-MLP hidden ----
        {
            const float4 p4 = *reinterpret_cast<const float4*>(&s_pos[bb][ln8v * 4]);
            float acc = pb1j;
            acc += p4.x * s_pw1[0 * 8 + j];
            acc += p4.y * s_pw1[1 * 8 + j];
            acc += p4.z * s_pw1[2 * 8 + j];
            acc += p4.w * s_pw1[3 * 8 + j];
            s_ph[ln8v * 8 + j] = fmaxf(acc, 0.f);
        }
        PAIRBAR(barid);

        // ---- phase A2: attn hidden = relu(hk - hq + ph@Ap + cb) ----
        {
            float2 acc0 = mf2(s_hk[bb][ln8v * 8 + j] - s_hq[bb][ln * 8 + j] + cbj, 0.f);
            float2 acc1 = mf2(0.f, 0.f);
            const float4* phr = reinterpret_cast<const float4*>(s_ph + ln8v * 8);
            const float4  h0 = phr[0], h1 = phr[1];
            const float4* apr = reinterpret_cast<const float4*>(s_apT + j * 8);
            const float4  a0 = apr[0], a1 = apr[1];
            acc0 = ffma2(mf2(h0.x, h0.y), mf2(a0.x, a0.y), acc0);
            acc1 = ffma2(mf2(h0.z, h0.w), mf2(a0.z, a0.w), acc1);
            acc0 = ffma2(mf2(h1.x, h1.y), mf2(a1.x, a1.y), acc0);
            acc1 = ffma2(mf2(h1.z, h1.w), mf2(a1.z, a1.w), acc1);
            s_hh[ln8v * 8 + j] = fmaxf((acc0.x + acc1.x) + (acc0.y + acc1.y), 0.f);
        }
        PAIRBAR(barid);

        // ---- phase B: logits + val, softmax over V; write to s_xall ----
        {
            const int4 m0i = *reinterpret_cast<const int4*>(&s_mask[bb][ln * 8]);
            const int4 m1i = *reinterpret_cast<const int4*>(&s_mask[bb][ln * 8 + 4]);
            int mbits = 0;
            mbits |= (m0i.x != 0) << 0; mbits |= (m0i.y != 0) << 1;
            mbits |= (m0i.z != 0) << 2; mbits |= (m0i.w != 0) << 3;
            mbits |= (m1i.x != 0) << 4; mbits |= (m1i.y != 0) << 5;
            mbits |= (m1i.z != 0) << 6; mbits |= (m1i.w != 0) << 7;

            float logit[8], val[8];
            #pragma unroll
            for (int v = 0; v < 8; ++v) {
                const int rv = ln * 8 + v;
                const float4* hhr = reinterpret_cast<const float4*>(s_hh + rv * 8);
                const float4 h0 = hhr[0], h1 = hhr[1];
                float2 a2 = ffma2(mf2(h0.x, h0.y), aw2r[0], mf2(ab2d, 0.f));
                float2 a3 = ffma2(mf2(h0.z, h0.w), aw2r[1], mf2(0.f, 0.f));
                a2 = ffma2(mf2(h1.x, h1.y), aw2r[2], a2);
                a3 = ffma2(mf2(h1.z, h1.w), aw2r[3], a3);

                const float4* phr = reinterpret_cast<const float4*>(s_ph + rv * 8);
                const float4 p0 = phr[0], p1 = phr[1];
                float2 pv = ffma2(mf2(p0.x, p0.y), pw2r[0], mf2(pb2d, 0.f));
                float2 pw = ffma2(mf2(p0.z, p0.w), pw2r[1], mf2(0.f, 0.f));
                pv = ffma2(mf2(p1.x, p1.y), pw2r[2], pv);
                pw = ffma2(mf2(p1.z, p1.w), pw2r[3], pw);

                logit[v] = ((mbits >> v) & 1) ? ((a2.x + a3.x) + (a2.y + a3.y)) : -1e9f;
                val[v] = s_vh[bb][rv * 64 + d] + (pv.x + pw.x) + (pv.y + pw.y);
            }
            const float m01 = fmaxf(fmaxf(logit[0], logit[1]), fmaxf(logit[2], logit[3]));
            const float m23 = fmaxf(fmaxf(logit[4], logit[5]), fmaxf(logit[6], logit[7]));
            const float m = fmaxf(m01, m23);
            float ev[8];
            #pragma unroll
            for (int v = 0; v < 8; ++v) ev[v] = __expf(logit[v] - m);
            const float ssum = ((ev[0] + ev[1]) + (ev[2] + ev[3]))
                             + ((ev[4] + ev[5]) + (ev[6] + ev[7]));
            const float wacc = ((ev[0] * val[0] + ev[1] * val[1]) + (ev[2] * val[2] + ev[3] * val[3]))
                             + ((ev[4] * val[4] + ev[5] * val[5]) + (ev[6] * val[6] + ev[7] * val[7]));
            s_xall[(chunk * 4 + ln) * 65 + d] = __fdividef(wacc, ssum);
        }
        // next iteration's CPWAIT0 + __syncthreads closes this chunk
    }
    __syncthreads();

    // ---- deferred output GEMM: 32 rows x 64 d; out_w via __ldg ----
    {
        const int dblk = (tid & 15) * 4;
        const int rp = tid >> 4;                 // 0..15
        const float4 ob4 = *reinterpret_cast<const float4*>(out_b + dblk);
        float2 a0 = mf2(ob4.x, ob4.y), a1 = mf2(ob4.z, ob4.w);
        float2 b0 = a0, b1 = a1;
        const float* x0p = s_xall + rp * 65;
        const float* x1p = s_xall + (rp + 16) * 65;
        #pragma unroll
        for (int c = 0; c < 64; ++c) {
            const float4 w4 = __ldg(reinterpret_cast<const float4*>(out_w + c * 64 + dblk));
            const float2 wlo = mf2(w4.x, w4.y), whi = mf2(w4.z, w4.w);
            const float xv0 = x0p[c], xv1 = x1p[c];
            a0 = ffma2(mf2(xv0, xv0), wlo, a0);
            a1 = ffma2(mf2(xv0, xv0), whi, a1);
            b0 = ffma2(mf2(xv1, xv1), wlo, b0);
            b1 = ffma2(mf2(xv1, xv1), whi, b1);
        }
        const long nb0 = (long)b * 64 + nbase;
        float4 o;
        o.x = a0.x; o.y = a0.y; o.z = a1.x; o.w = a1.y;
        *reinterpret_cast<float4*>(out + (nb0 + rp) * 64 + dblk) = o;
        o.x = b0.x; o.y = b0.y; o.z = b1.x; o.w = b1.y;
        *reinterpret_cast<float4*>(out + (nb0 + rp + 16) * 64 + dblk) = o;
    }
}

extern "C" void kernel_launch(void* const* d_in, const int* in_sizes, int n_in,
                              void* d_out, int out_size)
{
    const float* q        = (const float*)d_in[0];
    const float* k        = (const float*)d_in[1];
    const float* pos      = (const float*)d_in[2];
    const float* strength = (const float*)d_in[3];
    const float* q_tbl    = (const float*)d_in[4];
    const float* k_tbl    = (const float*)d_in[5];
    const float* v_tbl    = (const float*)d_in[6];
    const float* pos_w1   = (const float*)d_in[7];
    const float* pos_b1   = (const float*)d_in[8];
    const float* pos_w2   = (const float*)d_in[9];
    const float* pos_b2   = (const float*)d_in[10];
    const float* attn_w1  = (const float*)d_in[11];
    const float* attn_b1  = (const float*)d_in[12];
    const float* attn_w2  = (const float*)d_in[13];
    const float* attn_b2  = (const float*)d_in[14];
    const float* out_w    = (const float*)d_in[15];
    const float* out_b    = (const float*)d_in[16];
    const float* str_w    = (const float*)d_in[17];
    const float* str_b    = (const float*)d_in[18];
    const int*   mask     = (const int*)d_in[19];
    const int*   embed_id = (const int*)d_in[20];
    float* out = (float*)d_out;

    static bool attr_set = false;
    if (!attr_set) {
        cudaFuncSetAttribute(vh_kernel, cudaFuncAttributeMaxDynamicSharedMemorySize, VBYTES);
        attr_set = true;
    }

    precompute_kernel<<<4, 256>>>(strength, str_w, str_b, q_tbl, k_tbl, v_tbl,
                                  attn_w1, attn_b1, pos_w2, pos_b2, embed_id);

    vh_kernel<<<3072, 256, VBYTES>>>(k, q);

    dim3 grid(BQ, 2);
    attn_main<<<grid, 256>>>(pos,
                             pos_w1, pos_b1, pos_w2, pos_b2,
                             attn_w2, attn_b2, out_w, out_b,
                             mask, out);
}